// round 1
// baseline (speedup 1.0000x reference)
#include <cuda_runtime.h>
#include <cuda_bf16.h>
#include <cstdint>

// Problem constants (fixed by the dataset)
#define NN 50000
#define NE 800000
#define DIM 128
#define KK 5000
#define MBIG 1600002LL   // 2*E + 2

// ---------------- device scratch ----------------
__device__ float g_h1[NN * DIM];     // x @ W1
__device__ float g_x1[NN * DIM];     // relu(gcn1)
__device__ float g_agg[NN * DIM];    // gcn1 edge aggregation
__device__ float g_raw[NN];          // x1 @ w_score
__device__ int   g_deg_in[NN];       // bincount(col)  (gcn1 degree, before +1 self loop)
__device__ int   g_deg_row[NN];      // bincount(row)  (pooling degree)
__device__ int   g_keep[NN];
__device__ int   g_cid[NN];
__device__ unsigned long long g_best[NN];
__device__ float g_sums[KK * DIM];
__device__ int   g_cnts[KK];
__device__ float g_xp[KK * DIM];     // pooled means
__device__ float g_h2[KK * DIM];     // x_p @ W2
__device__ float g_agg2[KK * DIM];   // gcn2 aggregation (and final x_p2 in place)
__device__ int   g_deg2[KK];
__device__ unsigned long long g_kth_key;
__device__ int   g_counter;
__device__ int   g_maxdeg_kept;
__device__ unsigned long long g_fb_key;
__device__ int   g_fallback_cid;

// ---------------- helpers ----------------
__device__ __forceinline__ unsigned long long make_key(float v, int i) {
    unsigned u = __float_as_uint(v);
    u = (u & 0x80000000u) ? ~u : (u | 0x80000000u);   // monotonic float
    return ((unsigned long long)u << 32) | (unsigned long long)(0xFFFFFFFFu - (unsigned)i);
}

// ---------------- init ----------------
__global__ void k_zero_all() {
    int i = blockIdx.x * blockDim.x + threadIdx.x;
    if (i < NN * DIM) g_agg[i] = 0.f;
    if (i < KK * DIM) { g_sums[i] = 0.f; g_agg2[i] = 0.f; }
    if (i < NN) { g_deg_in[i] = 0; g_deg_row[i] = 0; g_best[i] = 0ULL; }
    if (i < KK) { g_cnts[i] = 0; g_deg2[i] = 0; }
    if (i == 0) { g_counter = 0; g_maxdeg_kept = 0; g_fb_key = 0ULL; }
}

// ---------------- degree counting ----------------
__global__ void k_deg(const int* __restrict__ row, const int* __restrict__ col) {
    int e = blockIdx.x * blockDim.x + threadIdx.x;
    if (e >= NE) return;
    atomicAdd(&g_deg_in[col[e]], 1);
    atomicAdd(&g_deg_row[row[e]], 1);
}

// ---------------- generic SGEMM: C[M,128] = A[M,128] @ B[128,128] ----------------
__global__ void k_gemm128(const float* __restrict__ A, const float* __restrict__ B,
                          float* __restrict__ C, int M) {
    __shared__ float As[8][65];   // As[k][i] transposed tile (64 rows x 8 k)
    __shared__ float Bs[8][128];
    int row0 = blockIdx.x * 64;
    int tid = threadIdx.x;
    int tx = tid & 31;            // 32 col-groups of 4
    int ty = tid >> 5;            // 8 row-groups of 8
    float acc[8][4];
    #pragma unroll
    for (int r = 0; r < 8; r++)
        #pragma unroll
        for (int c = 0; c < 4; c++) acc[r][c] = 0.f;

    for (int kk = 0; kk < 128; kk += 8) {
        #pragma unroll
        for (int t = tid; t < 512; t += 256) {
            int i = t >> 3, k = t & 7;
            int r = row0 + i;
            As[k][i] = (r < M) ? A[r * 128 + kk + k] : 0.f;
        }
        #pragma unroll
        for (int t = tid; t < 1024; t += 256) {
            int k = t >> 7, j = t & 127;
            Bs[k][j] = B[(kk + k) * 128 + j];
        }
        __syncthreads();
        #pragma unroll
        for (int k = 0; k < 8; k++) {
            float a[8], b[4];
            #pragma unroll
            for (int r = 0; r < 8; r++) a[r] = As[k][ty * 8 + r];
            #pragma unroll
            for (int c = 0; c < 4; c++) b[c] = Bs[k][tx * 4 + c];
            #pragma unroll
            for (int r = 0; r < 8; r++)
                #pragma unroll
                for (int c = 0; c < 4; c++) acc[r][c] += a[r] * b[c];
        }
        __syncthreads();
    }
    #pragma unroll
    for (int r = 0; r < 8; r++) {
        int rr = row0 + ty * 8 + r;
        if (rr < M) {
            float4 v = make_float4(acc[r][0], acc[r][1], acc[r][2], acc[r][3]);
            *reinterpret_cast<float4*>(&C[rr * 128 + tx * 4]) = v;
        }
    }
}

// ---------------- GCN1 edge aggregation (warp per edge) ----------------
__global__ void k_agg1(const int* __restrict__ row, const int* __restrict__ col) {
    int w = (blockIdx.x * blockDim.x + threadIdx.x) >> 5;
    int lane = threadIdx.x & 31;
    if (w >= NE) return;
    int r = row[w], c = col[w];
    float norm = rsqrtf((float)(g_deg_in[r] + 1)) * rsqrtf((float)(g_deg_in[c] + 1));
    float4 v = *reinterpret_cast<const float4*>(&g_h1[r * 128 + lane * 4]);
    float* dst = &g_agg[c * 128 + lane * 4];
    atomicAdd(dst + 0, norm * v.x);
    atomicAdd(dst + 1, norm * v.y);
    atomicAdd(dst + 2, norm * v.z);
    atomicAdd(dst + 3, norm * v.w);
}

// ---------------- x1 = relu(agg + dinv^2*h1 + b1); raw = x1 . w_score ----------------
__global__ void k_x1raw(const float* __restrict__ b1, const float* __restrict__ ws) {
    int i = (blockIdx.x * blockDim.x + threadIdx.x) >> 5;
    int lane = threadIdx.x & 31;
    if (i >= NN) return;
    float di2 = 1.f / (float)(g_deg_in[i] + 1);
    float4 h = *reinterpret_cast<const float4*>(&g_h1[i * 128 + lane * 4]);
    float4 a = *reinterpret_cast<const float4*>(&g_agg[i * 128 + lane * 4]);
    float4 bb = *reinterpret_cast<const float4*>(&b1[lane * 4]);
    float4 x;
    x.x = fmaxf(a.x + di2 * h.x + bb.x, 0.f);
    x.y = fmaxf(a.y + di2 * h.y + bb.y, 0.f);
    x.z = fmaxf(a.z + di2 * h.z + bb.z, 0.f);
    x.w = fmaxf(a.w + di2 * h.w + bb.w, 0.f);
    *reinterpret_cast<float4*>(&g_x1[i * 128 + lane * 4]) = x;
    float4 w4 = *reinterpret_cast<const float4*>(&ws[lane * 4]);
    float p = x.x * w4.x + x.y * w4.y + x.z * w4.z + x.w * w4.w;
    #pragma unroll
    for (int o = 16; o > 0; o >>= 1) p += __shfl_xor_sync(0xFFFFFFFFu, p, o);
    if (lane == 0) g_raw[i] = p;
}

// ---------------- top-K radix select on 64-bit keys (single block) ----------------
__global__ void k_select() {
    __shared__ int hist[256];
    __shared__ unsigned long long sh_prefix;
    __shared__ int sh_k;
    if (threadIdx.x == 0) { sh_prefix = 0ULL; sh_k = KK; }
    __syncthreads();
    for (int pos = 7; pos >= 0; --pos) {
        if (threadIdx.x < 256) hist[threadIdx.x] = 0;
        __syncthreads();
        unsigned long long pref = sh_prefix;
        for (int i = threadIdx.x; i < NN; i += blockDim.x) {
            unsigned long long key = make_key(g_raw[i], i);
            unsigned long long hi = (pos == 7) ? 0ULL : (key >> ((pos + 1) * 8));
            if (hi == pref)
                atomicAdd(&hist[(int)((key >> (pos * 8)) & 255)], 1);
        }
        __syncthreads();
        if (threadIdx.x == 0) {
            int k = sh_k;
            int b = 255;
            for (;; b--) {
                int c = hist[b];
                if (c >= k) break;
                k -= c;
            }
            sh_k = k;
            sh_prefix = (pref << 8) | (unsigned long long)b;
        }
        __syncthreads();
    }
    if (threadIdx.x == 0) g_kth_key = sh_prefix;
}

// ---------------- keep mask + cluster labels + max kept degree ----------------
__global__ void k_keep_label() {
    int i = blockIdx.x * blockDim.x + threadIdx.x;
    if (i >= NN) return;
    unsigned long long key = make_key(g_raw[i], i);
    int kp = (key >= g_kth_key) ? 1 : 0;
    g_keep[i] = kp;
    if (kp) {
        int lbl = atomicAdd(&g_counter, 1);
        g_cid[i] = lbl;
        atomicMax(&g_maxdeg_kept, g_deg_row[i]);
    }
}

// ---------------- fallback: kept node with max deg_row, ties -> max (raw, -idx) ----------------
__global__ void k_fbkey() {
    int i = blockIdx.x * blockDim.x + threadIdx.x;
    if (i >= NN) return;
    if (g_keep[i] && g_deg_row[i] == g_maxdeg_kept)
        atomicMax(&g_fb_key, make_key(g_raw[i], i));
}
__global__ void k_fbdecode() {
    int node = (int)(0xFFFFFFFFu - (unsigned)(g_fb_key & 0xFFFFFFFFull));
    g_fallback_cid = g_cid[node];
}

// ---------------- best kept neighbor per node (packed segment_max) ----------------
__global__ void k_best(const int* __restrict__ row, const int* __restrict__ col) {
    int e = blockIdx.x * blockDim.x + threadIdx.x;
    if (e >= NE) return;
    int r = row[e], c = col[e];
    // direction 0: owner=r, neigh=c, order=2e
    if (g_keep[c]) {
        long long comp = (long long)g_deg_row[c] * MBIG + (MBIG - 1 - 2LL * e);
        unsigned long long key = ((unsigned long long)comp << 17) | (unsigned)c;
        atomicMax(&g_best[r], key);
    }
    // direction 1: owner=c, neigh=r, order=2e+1
    if (g_keep[r]) {
        long long comp = (long long)g_deg_row[r] * MBIG + (MBIG - 2 - 2LL * e);
        unsigned long long key = ((unsigned long long)comp << 17) | (unsigned)r;
        atomicMax(&g_best[c], key);
    }
}

__global__ void k_assign() {
    int i = blockIdx.x * blockDim.x + threadIdx.x;
    if (i >= NN) return;
    if (g_keep[i]) return;
    unsigned long long b = g_best[i];
    g_cid[i] = (b > 0ULL) ? g_cid[(int)(b & 0x1FFFFull)] : g_fallback_cid;
}

// ---------------- mean pooling of gated features ----------------
__global__ void k_pool() {
    int i = (blockIdx.x * blockDim.x + threadIdx.x) >> 5;
    int lane = threadIdx.x & 31;
    if (i >= NN) return;
    int c = g_cid[i];
    float t = tanhf(g_raw[i]);
    float4 x = *reinterpret_cast<const float4*>(&g_x1[i * 128 + lane * 4]);
    float* dst = &g_sums[c * 128 + lane * 4];
    atomicAdd(dst + 0, t * x.x);
    atomicAdd(dst + 1, t * x.y);
    atomicAdd(dst + 2, t * x.z);
    atomicAdd(dst + 3, t * x.w);
    if (lane == 0) atomicAdd(&g_cnts[c], 1);
}

__global__ void k_xp() {
    int c = (blockIdx.x * blockDim.x + threadIdx.x) >> 5;
    int lane = threadIdx.x & 31;
    if (c >= KK) return;
    float inv = 1.f / (float)max(g_cnts[c], 1);
    float4 s = *reinterpret_cast<const float4*>(&g_sums[c * 128 + lane * 4]);
    s.x *= inv; s.y *= inv; s.z *= inv; s.w *= inv;
    *reinterpret_cast<float4*>(&g_xp[c * 128 + lane * 4]) = s;
}

// ---------------- coarse graph degree ----------------
__global__ void k_deg2(const int* __restrict__ row, const int* __restrict__ col) {
    int e = blockIdx.x * blockDim.x + threadIdx.x;
    if (e >= NE) return;
    int cu = g_cid[row[e]], cv = g_cid[col[e]];
    if (cu != cv) atomicAdd(&g_deg2[cv], 1);
}

// ---------------- coarse aggregation (warp per edge) ----------------
__global__ void k_agg2(const int* __restrict__ row, const int* __restrict__ col) {
    int w = (blockIdx.x * blockDim.x + threadIdx.x) >> 5;
    int lane = threadIdx.x & 31;
    if (w >= NE) return;
    int cu = g_cid[row[w]], cv = g_cid[col[w]];
    if (cu == cv) return;
    float norm = rsqrtf((float)(g_deg2[cu] + 1)) * rsqrtf((float)(g_deg2[cv] + 1));
    float4 v = *reinterpret_cast<const float4*>(&g_h2[cu * 128 + lane * 4]);
    float* dst = &g_agg2[cv * 128 + lane * 4];
    atomicAdd(dst + 0, norm * v.x);
    atomicAdd(dst + 1, norm * v.y);
    atomicAdd(dst + 2, norm * v.z);
    atomicAdd(dst + 3, norm * v.w);
}

// ---------------- x_p2 = agg2 + dinv^2*h2 + b2 (in place into g_agg2) ----------------
__global__ void k_xp2(const float* __restrict__ b2) {
    int c = (blockIdx.x * blockDim.x + threadIdx.x) >> 5;
    int lane = threadIdx.x & 31;
    if (c >= KK) return;
    float di2 = 1.f / (float)(g_deg2[c] + 1);
    float4 h = *reinterpret_cast<const float4*>(&g_h2[c * 128 + lane * 4]);
    float4 a = *reinterpret_cast<const float4*>(&g_agg2[c * 128 + lane * 4]);
    float4 bb = *reinterpret_cast<const float4*>(&b2[lane * 4]);
    a.x += di2 * h.x + bb.x;
    a.y += di2 * h.y + bb.y;
    a.z += di2 * h.z + bb.z;
    a.w += di2 * h.w + bb.w;
    *reinterpret_cast<float4*>(&g_agg2[c * 128 + lane * 4]) = a;
}

// ---------------- final: out += x_p2[cid] + b_skip ----------------
__global__ void k_final(float* __restrict__ out, const float* __restrict__ bsk) {
    int i = (blockIdx.x * blockDim.x + threadIdx.x) >> 5;
    int lane = threadIdx.x & 31;
    if (i >= NN) return;
    int c = g_cid[i];
    float4 o = *reinterpret_cast<const float4*>(&out[i * 128 + lane * 4]);
    float4 p = *reinterpret_cast<const float4*>(&g_agg2[c * 128 + lane * 4]);
    float4 bb = *reinterpret_cast<const float4*>(&bsk[lane * 4]);
    o.x += p.x + bb.x;
    o.y += p.y + bb.y;
    o.z += p.z + bb.z;
    o.w += p.w + bb.w;
    *reinterpret_cast<float4*>(&out[i * 128 + lane * 4]) = o;
}

__global__ void k_tail(float* __restrict__ out, int start, int total) {
    int i = start + blockIdx.x * blockDim.x + threadIdx.x;
    if (i < total) out[i] = 0.f;
}

// ---------------- launch ----------------
extern "C" void kernel_launch(void* const* d_in, const int* in_sizes, int n_in,
                              void* d_out, int out_size) {
    const float* x      = (const float*)d_in[0];
    const int*   ei     = (const int*)d_in[1];
    const float* W1     = (const float*)d_in[2];
    const float* b1     = (const float*)d_in[3];
    const float* W2     = (const float*)d_in[4];
    const float* b2     = (const float*)d_in[5];
    const float* wscore = (const float*)d_in[6];
    const float* Wskip  = (const float*)d_in[7];
    const float* bskip  = (const float*)d_in[8];
    float* out = (float*)d_out;

    const int* row = ei;
    const int* col = ei + NE;

    const int T = 256;
    const int nwarpN = (NN * 32 + T - 1) / T;   // warp-per-node grids
    const int nwarpE = (NE * 32 + T - 1) / T;   // warp-per-edge grids
    const int nwarpK = (KK * 32 + T - 1) / T;

    k_zero_all<<<(NN * DIM + T - 1) / T, T>>>();
    k_deg<<<(NE + T - 1) / T, T>>>(row, col);

    // GCN layer 1
    float* h1;  cudaGetSymbolAddress((void**)&h1, g_h1);
    float* x1;  cudaGetSymbolAddress((void**)&x1, g_x1);
    float* xp;  cudaGetSymbolAddress((void**)&xp, g_xp);
    float* h2;  cudaGetSymbolAddress((void**)&h2, g_h2);

    k_gemm128<<<(NN + 63) / 64, 256>>>(x, W1, h1, NN);
    k_agg1<<<nwarpE, T>>>(row, col);
    k_x1raw<<<nwarpN, T>>>(b1, wscore);

    // top-K + clustering
    k_select<<<1, 1024>>>();
    k_keep_label<<<(NN + T - 1) / T, T>>>();
    k_fbkey<<<(NN + T - 1) / T, T>>>();
    k_fbdecode<<<1, 1>>>();
    k_best<<<(NE + T - 1) / T, T>>>(row, col);
    k_assign<<<(NN + T - 1) / T, T>>>();

    // pooling
    k_pool<<<nwarpN, T>>>();
    k_xp<<<nwarpK, T>>>();

    // GCN layer 2 on coarse graph
    k_gemm128<<<(KK + 63) / 64, 256>>>(xp, W2, h2, KK);
    k_deg2<<<(NE + T - 1) / T, T>>>(row, col);
    k_agg2<<<nwarpE, T>>>(row, col);
    k_xp2<<<nwarpK, T>>>(b2);

    // skip GEMM straight into output, then broadcast-add coarse features
    k_gemm128<<<(NN + 63) / 64, 256>>>(x1, Wskip, out, NN);
    k_final<<<nwarpN, T>>>(out, bskip);

    if (out_size > NN * DIM) {
        int rem = out_size - NN * DIM;
        k_tail<<<(rem + T - 1) / T, T>>>(out, NN * DIM, out_size);
    }
}

// round 2
// speedup vs baseline: 2.6056x; 2.6056x over previous
#include <cuda_runtime.h>
#include <cuda_bf16.h>
#include <cstdint>

// Problem constants (fixed by the dataset)
#define NN 50000
#define NE 800000
#define DIM 128
#define KK 5000
#define MBIG 1600002LL   // 2*E + 2

// ---------------- device scratch ----------------
__device__ float g_h1[NN * DIM];     // x @ W1
__device__ float g_x1[NN * DIM];     // relu(gcn1)
__device__ float g_agg[NN * DIM];    // gcn1 edge aggregation
__device__ float g_raw[NN];          // x1 @ w_score
__device__ int   g_deg_in[NN];       // bincount(col)  (gcn1 degree, before +1 self loop)
__device__ int   g_deg_row[NN];      // bincount(row)  (pooling degree)
__device__ int   g_keep[NN];
__device__ int   g_cid[NN];
__device__ unsigned long long g_best[NN];
__device__ float g_sums[KK * DIM];
__device__ int   g_cnts[KK];
__device__ float g_xp[KK * DIM];     // pooled means
__device__ float g_h2[KK * DIM];     // x_p @ W2
__device__ float g_agg2[KK * DIM];   // gcn2 aggregation (and final x_p2 in place)
__device__ int   g_deg2[KK];
__device__ unsigned long long g_kth_key;
__device__ int   g_counter;
__device__ int   g_maxdeg_kept;
__device__ unsigned long long g_fb_key;
__device__ int   g_fallback_cid;

// ---------------- helpers ----------------
__device__ __forceinline__ unsigned mono32(float v) {
    unsigned u = __float_as_uint(v);
    return (u & 0x80000000u) ? ~u : (u | 0x80000000u);   // monotonic float
}
__device__ __forceinline__ unsigned long long make_key(float v, int i) {
    return ((unsigned long long)mono32(v) << 32) |
           (unsigned long long)(0xFFFFFFFFu - (unsigned)i);
}
// vectorized global float4 reduction (sm_90+)
__device__ __forceinline__ void red_add_v4(float* addr, float a, float b, float c, float d) {
    asm volatile("red.global.add.v4.f32 [%0], {%1,%2,%3,%4};"
                 :: "l"(addr), "f"(a), "f"(b), "f"(c), "f"(d) : "memory");
}

// ---------------- init ----------------
__global__ void k_zero_all() {
    int i = blockIdx.x * blockDim.x + threadIdx.x;
    int i4 = i * 4;
    if (i4 < NN * DIM) *reinterpret_cast<float4*>(&g_agg[i4]) = make_float4(0.f, 0.f, 0.f, 0.f);
    if (i4 < KK * DIM) {
        *reinterpret_cast<float4*>(&g_sums[i4]) = make_float4(0.f, 0.f, 0.f, 0.f);
        *reinterpret_cast<float4*>(&g_agg2[i4]) = make_float4(0.f, 0.f, 0.f, 0.f);
    }
    if (i < NN) { g_deg_in[i] = 0; g_deg_row[i] = 0; g_best[i] = 0ULL; }
    if (i < KK) { g_cnts[i] = 0; g_deg2[i] = 0; }
    if (i == 0) { g_counter = 0; g_maxdeg_kept = 0; g_fb_key = 0ULL; }
}

// ---------------- degree counting ----------------
__global__ void k_deg(const int* __restrict__ row, const int* __restrict__ col) {
    int e = blockIdx.x * blockDim.x + threadIdx.x;
    if (e >= NE) return;
    atomicAdd(&g_deg_in[col[e]], 1);
    atomicAdd(&g_deg_row[row[e]], 1);
}

// ---------------- generic SGEMM: C[M,128] = A[M,128] @ B[128,128] ----------------
__global__ void k_gemm128(const float* __restrict__ A, const float* __restrict__ B,
                          float* __restrict__ C, int M) {
    __shared__ float As[16][65];   // As[k][i] transposed tile (64 rows x 16 k)
    __shared__ float Bs[16][128];
    int row0 = blockIdx.x * 64;
    int tid = threadIdx.x;
    int tx = tid & 31;            // 32 col-groups of 4
    int ty = tid >> 5;            // 8 row-groups of 8
    float acc[8][4];
    #pragma unroll
    for (int r = 0; r < 8; r++)
        #pragma unroll
        for (int c = 0; c < 4; c++) acc[r][c] = 0.f;

    // A-load mapping: each thread loads one float4 of A per chunk
    int ai = tid >> 2;            // row within tile 0..63
    int ak = (tid & 3) * 4;       // k offset (float4)

    for (int kk = 0; kk < 128; kk += 16) {
        {
            int r = row0 + ai;
            float4 v = (r < M) ? *reinterpret_cast<const float4*>(&A[r * 128 + kk + ak])
                               : make_float4(0.f, 0.f, 0.f, 0.f);
            As[ak + 0][ai] = v.x;
            As[ak + 1][ai] = v.y;
            As[ak + 2][ai] = v.z;
            As[ak + 3][ai] = v.w;
        }
        #pragma unroll
        for (int t = tid; t < 512; t += 256) {
            int k = t >> 5, j = (t & 31) * 4;
            float4 v = *reinterpret_cast<const float4*>(&B[(kk + k) * 128 + j]);
            *reinterpret_cast<float4*>(&Bs[k][j]) = v;
        }
        __syncthreads();
        #pragma unroll
        for (int k = 0; k < 16; k++) {
            float a[8], b[4];
            #pragma unroll
            for (int r = 0; r < 8; r++) a[r] = As[k][ty * 8 + r];
            #pragma unroll
            for (int c = 0; c < 4; c++) b[c] = Bs[k][tx * 4 + c];
            #pragma unroll
            for (int r = 0; r < 8; r++)
                #pragma unroll
                for (int c = 0; c < 4; c++) acc[r][c] += a[r] * b[c];
        }
        __syncthreads();
    }
    #pragma unroll
    for (int r = 0; r < 8; r++) {
        int rr = row0 + ty * 8 + r;
        if (rr < M) {
            float4 v = make_float4(acc[r][0], acc[r][1], acc[r][2], acc[r][3]);
            *reinterpret_cast<float4*>(&C[rr * 128 + tx * 4]) = v;
        }
    }
}

// ---------------- GCN1 edge aggregation (warp per edge, vector RED) ----------------
__global__ void k_agg1(const int* __restrict__ row, const int* __restrict__ col) {
    int w = (blockIdx.x * blockDim.x + threadIdx.x) >> 5;
    int lane = threadIdx.x & 31;
    if (w >= NE) return;
    int r = row[w], c = col[w];
    float norm = rsqrtf((float)(g_deg_in[r] + 1)) * rsqrtf((float)(g_deg_in[c] + 1));
    float4 v = *reinterpret_cast<const float4*>(&g_h1[r * 128 + lane * 4]);
    red_add_v4(&g_agg[c * 128 + lane * 4], norm * v.x, norm * v.y, norm * v.z, norm * v.w);
}

// ---------------- x1 = relu(agg + dinv^2*h1 + b1); raw = x1 . w_score ----------------
__global__ void k_x1raw(const float* __restrict__ b1, const float* __restrict__ ws) {
    int i = (blockIdx.x * blockDim.x + threadIdx.x) >> 5;
    int lane = threadIdx.x & 31;
    if (i >= NN) return;
    float di2 = 1.f / (float)(g_deg_in[i] + 1);
    float4 h = *reinterpret_cast<const float4*>(&g_h1[i * 128 + lane * 4]);
    float4 a = *reinterpret_cast<const float4*>(&g_agg[i * 128 + lane * 4]);
    float4 bb = *reinterpret_cast<const float4*>(&b1[lane * 4]);
    float4 x;
    x.x = fmaxf(a.x + di2 * h.x + bb.x, 0.f);
    x.y = fmaxf(a.y + di2 * h.y + bb.y, 0.f);
    x.z = fmaxf(a.z + di2 * h.z + bb.z, 0.f);
    x.w = fmaxf(a.w + di2 * h.w + bb.w, 0.f);
    *reinterpret_cast<float4*>(&g_x1[i * 128 + lane * 4]) = x;
    float4 w4 = *reinterpret_cast<const float4*>(&ws[lane * 4]);
    float p = x.x * w4.x + x.y * w4.y + x.z * w4.z + x.w * w4.w;
    #pragma unroll
    for (int o = 16; o > 0; o >>= 1) p += __shfl_xor_sync(0xFFFFFFFFu, p, o);
    if (lane == 0) g_raw[i] = p;
}

// ---------------- top-K radix select, smem-cached keys (single block) ----------------
__global__ void k_select() {
    extern __shared__ unsigned sv[];      // NN monotonic 32-bit scores
    __shared__ int hist[256];
    __shared__ unsigned long long sh_prefix;
    __shared__ int sh_k;
    for (int i = threadIdx.x; i < NN; i += blockDim.x) sv[i] = mono32(g_raw[i]);
    if (threadIdx.x == 0) { sh_prefix = 0ULL; sh_k = KK; }
    __syncthreads();
    for (int pos = 7; pos >= 0; --pos) {
        if (threadIdx.x < 256) hist[threadIdx.x] = 0;
        __syncthreads();
        unsigned long long pref = sh_prefix;
        for (int i = threadIdx.x; i < NN; i += blockDim.x) {
            unsigned long long key = ((unsigned long long)sv[i] << 32) |
                                     (unsigned long long)(0xFFFFFFFFu - (unsigned)i);
            unsigned long long hi = (pos == 7) ? 0ULL : (key >> ((pos + 1) * 8));
            if (hi == pref)
                atomicAdd(&hist[(int)((key >> (pos * 8)) & 255)], 1);
        }
        __syncthreads();
        if (threadIdx.x == 0) {
            int k = sh_k;
            int b = 255;
            for (;; b--) {
                int c = hist[b];
                if (c >= k) break;
                k -= c;
            }
            sh_k = k;
            sh_prefix = (pref << 8) | (unsigned long long)b;
        }
        __syncthreads();
    }
    if (threadIdx.x == 0) g_kth_key = sh_prefix;
}

// ---------------- keep mask + cluster labels + max kept degree ----------------
__global__ void k_keep_label() {
    int i = blockIdx.x * blockDim.x + threadIdx.x;
    if (i >= NN) return;
    unsigned long long key = make_key(g_raw[i], i);
    int kp = (key >= g_kth_key) ? 1 : 0;
    g_keep[i] = kp;
    if (kp) {
        int lbl = atomicAdd(&g_counter, 1);
        g_cid[i] = lbl;
        atomicMax(&g_maxdeg_kept, g_deg_row[i]);
    }
}

// ---------------- fallback: kept node with max deg_row, ties -> max (raw, -idx) ----------------
__global__ void k_fbkey() {
    int i = blockIdx.x * blockDim.x + threadIdx.x;
    if (i >= NN) return;
    if (g_keep[i] && g_deg_row[i] == g_maxdeg_kept)
        atomicMax(&g_fb_key, make_key(g_raw[i], i));
}
__global__ void k_fbdecode() {
    int node = (int)(0xFFFFFFFFu - (unsigned)(g_fb_key & 0xFFFFFFFFull));
    g_fallback_cid = g_cid[node];
}

// ---------------- best kept neighbor per node (packed segment_max) ----------------
__global__ void k_best(const int* __restrict__ row, const int* __restrict__ col) {
    int e = blockIdx.x * blockDim.x + threadIdx.x;
    if (e >= NE) return;
    int r = row[e], c = col[e];
    // direction 0: owner=r, neigh=c, order=2e
    if (g_keep[c]) {
        long long comp = (long long)g_deg_row[c] * MBIG + (MBIG - 1 - 2LL * e);
        unsigned long long key = ((unsigned long long)comp << 17) | (unsigned)c;
        atomicMax(&g_best[r], key);
    }
    // direction 1: owner=c, neigh=r, order=2e+1
    if (g_keep[r]) {
        long long comp = (long long)g_deg_row[r] * MBIG + (MBIG - 2 - 2LL * e);
        unsigned long long key = ((unsigned long long)comp << 17) | (unsigned)r;
        atomicMax(&g_best[c], key);
    }
}

__global__ void k_assign() {
    int i = blockIdx.x * blockDim.x + threadIdx.x;
    if (i >= NN) return;
    if (g_keep[i]) return;
    unsigned long long b = g_best[i];
    g_cid[i] = (b > 0ULL) ? g_cid[(int)(b & 0x1FFFFull)] : g_fallback_cid;
}

// ---------------- mean pooling of gated features (vector RED) ----------------
__global__ void k_pool() {
    int i = (blockIdx.x * blockDim.x + threadIdx.x) >> 5;
    int lane = threadIdx.x & 31;
    if (i >= NN) return;
    int c = g_cid[i];
    float t = tanhf(g_raw[i]);
    float4 x = *reinterpret_cast<const float4*>(&g_x1[i * 128 + lane * 4]);
    red_add_v4(&g_sums[c * 128 + lane * 4], t * x.x, t * x.y, t * x.z, t * x.w);
    if (lane == 0) atomicAdd(&g_cnts[c], 1);
}

__global__ void k_xp() {
    int c = (blockIdx.x * blockDim.x + threadIdx.x) >> 5;
    int lane = threadIdx.x & 31;
    if (c >= KK) return;
    float inv = 1.f / (float)max(g_cnts[c], 1);
    float4 s = *reinterpret_cast<const float4*>(&g_sums[c * 128 + lane * 4]);
    s.x *= inv; s.y *= inv; s.z *= inv; s.w *= inv;
    *reinterpret_cast<float4*>(&g_xp[c * 128 + lane * 4]) = s;
}

// ---------------- coarse graph degree ----------------
__global__ void k_deg2(const int* __restrict__ row, const int* __restrict__ col) {
    int e = blockIdx.x * blockDim.x + threadIdx.x;
    if (e >= NE) return;
    int cu = g_cid[row[e]], cv = g_cid[col[e]];
    if (cu != cv) atomicAdd(&g_deg2[cv], 1);
}

// ---------------- coarse aggregation (warp per edge, vector RED) ----------------
__global__ void k_agg2(const int* __restrict__ row, const int* __restrict__ col) {
    int w = (blockIdx.x * blockDim.x + threadIdx.x) >> 5;
    int lane = threadIdx.x & 31;
    if (w >= NE) return;
    int cu = g_cid[row[w]], cv = g_cid[col[w]];
    if (cu == cv) return;
    float norm = rsqrtf((float)(g_deg2[cu] + 1)) * rsqrtf((float)(g_deg2[cv] + 1));
    float4 v = *reinterpret_cast<const float4*>(&g_h2[cu * 128 + lane * 4]);
    red_add_v4(&g_agg2[cv * 128 + lane * 4], norm * v.x, norm * v.y, norm * v.z, norm * v.w);
}

// ---------------- x_p2 = agg2 + dinv^2*h2 + b2 (in place into g_agg2) ----------------
__global__ void k_xp2(const float* __restrict__ b2) {
    int c = (blockIdx.x * blockDim.x + threadIdx.x) >> 5;
    int lane = threadIdx.x & 31;
    if (c >= KK) return;
    float di2 = 1.f / (float)(g_deg2[c] + 1);
    float4 h = *reinterpret_cast<const float4*>(&g_h2[c * 128 + lane * 4]);
    float4 a = *reinterpret_cast<const float4*>(&g_agg2[c * 128 + lane * 4]);
    float4 bb = *reinterpret_cast<const float4*>(&b2[lane * 4]);
    a.x += di2 * h.x + bb.x;
    a.y += di2 * h.y + bb.y;
    a.z += di2 * h.z + bb.z;
    a.w += di2 * h.w + bb.w;
    *reinterpret_cast<float4*>(&g_agg2[c * 128 + lane * 4]) = a;
}

// ---------------- final: out += x_p2[cid] + b_skip ----------------
__global__ void k_final(float* __restrict__ out, const float* __restrict__ bsk) {
    int i = (blockIdx.x * blockDim.x + threadIdx.x) >> 5;
    int lane = threadIdx.x & 31;
    if (i >= NN) return;
    int c = g_cid[i];
    float4 o = *reinterpret_cast<const float4*>(&out[i * 128 + lane * 4]);
    float4 p = *reinterpret_cast<const float4*>(&g_agg2[c * 128 + lane * 4]);
    float4 bb = *reinterpret_cast<const float4*>(&bsk[lane * 4]);
    o.x += p.x + bb.x;
    o.y += p.y + bb.y;
    o.z += p.z + bb.z;
    o.w += p.w + bb.w;
    *reinterpret_cast<float4*>(&out[i * 128 + lane * 4]) = o;
}

__global__ void k_tail(float* __restrict__ out, int start, int total) {
    int i = start + blockIdx.x * blockDim.x + threadIdx.x;
    if (i < total) out[i] = 0.f;
}

// ---------------- launch ----------------
extern "C" void kernel_launch(void* const* d_in, const int* in_sizes, int n_in,
                              void* d_out, int out_size) {
    const float* x      = (const float*)d_in[0];
    const int*   ei     = (const int*)d_in[1];
    const float* W1     = (const float*)d_in[2];
    const float* b1     = (const float*)d_in[3];
    const float* W2     = (const float*)d_in[4];
    const float* b2     = (const float*)d_in[5];
    const float* wscore = (const float*)d_in[6];
    const float* Wskip  = (const float*)d_in[7];
    const float* bskip  = (const float*)d_in[8];
    float* out = (float*)d_out;

    const int* row = ei;
    const int* col = ei + NE;

    const int T = 256;
    const int nwarpN = (NN * 32 + T - 1) / T;   // warp-per-node grids
    const int nwarpE = (NE * 32 + T - 1) / T;   // warp-per-edge grids
    const int nwarpK = (KK * 32 + T - 1) / T;

    static int smem_set = 0;
    if (!smem_set) {
        cudaFuncSetAttribute(k_select, cudaFuncAttributeMaxDynamicSharedMemorySize,
                             NN * (int)sizeof(unsigned));
        smem_set = 1;
    }

    k_zero_all<<<(NN * DIM / 4 + T - 1) / T, T>>>();
    k_deg<<<(NE + T - 1) / T, T>>>(row, col);

    float* h1;  cudaGetSymbolAddress((void**)&h1, g_h1);
    float* x1;  cudaGetSymbolAddress((void**)&x1, g_x1);
    float* xp;  cudaGetSymbolAddress((void**)&xp, g_xp);
    float* h2;  cudaGetSymbolAddress((void**)&h2, g_h2);

    // GCN layer 1
    k_gemm128<<<(NN + 63) / 64, 256>>>(x, W1, h1, NN);
    k_agg1<<<nwarpE, T>>>(row, col);
    k_x1raw<<<nwarpN, T>>>(b1, wscore);

    // top-K + clustering
    k_select<<<1, 1024, NN * sizeof(unsigned)>>>();
    k_keep_label<<<(NN + T - 1) / T, T>>>();
    k_fbkey<<<(NN + T - 1) / T, T>>>();
    k_fbdecode<<<1, 1>>>();
    k_best<<<(NE + T - 1) / T, T>>>(row, col);
    k_assign<<<(NN + T - 1) / T, T>>>();

    // pooling
    k_pool<<<nwarpN, T>>>();
    k_xp<<<nwarpK, T>>>();

    // GCN layer 2 on coarse graph
    k_gemm128<<<(KK + 63) / 64, 256>>>(xp, W2, h2, KK);
    k_deg2<<<(NE + T - 1) / T, T>>>(row, col);
    k_agg2<<<nwarpE, T>>>(row, col);
    k_xp2<<<nwarpK, T>>>(b2);

    // skip GEMM straight into output, then broadcast-add coarse features
    k_gemm128<<<(NN + 63) / 64, 256>>>(x1, Wskip, out, NN);
    k_final<<<nwarpN, T>>>(out, bskip);

    if (out_size > NN * DIM) {
        int rem = out_size - NN * DIM;
        k_tail<<<(rem + T - 1) / T, T>>>(out, NN * DIM, out_size);
    }
}